// round 16
// baseline (speedup 1.0000x reference)
#include <cuda_runtime.h>
#include <cuda_fp16.h>
#include <math.h>
#include <stdint.h>

#define Bsz 64
#define TIN 128
#define TOUT 32
#define Vv 32000
#define Ee 512
#define Hh 1024
#define Aa 512
#define Ll 4
#define NSEG 8
#define SEGV (Vv / NSEG)

// GEMM tiling (fp16, k-paired u32 domain)
#define BK 32                   // halves per K-chunk
#define KU (BK / 2)             // 16 u32 rows per chunk
#define ASTU 20                 // A smem row stride (u32, pad 4)
#define NSTAGE 3

// ---------------- fp16 packed weights (filled per launch) ----------------
__device__ __align__(16) uint32_t g_Wl16[(size_t)(3 * Hh / 2) * Vv];
__device__ __align__(16) uint32_t g_Wih016[(2 * Hh + Ee) / 2 * 4 * Hh];
__device__ __align__(16) uint32_t g_Wihr16[3][(Hh / 2) * 4 * Hh];
__device__ __align__(16) uint32_t g_Whh16[Ll][(Hh / 2) * 4 * Hh];
__device__ __align__(16) uint32_t g_A1lo16[(Hh / 2) * Aa];
__device__ __align__(16) uint32_t g_A1hi16[Hh * Aa];
__device__ __align__(16) __half g_emb16[(size_t)Vv * Ee];
__device__ __align__(16) __half g_enc16[(size_t)TIN * Bsz * 2 * Hh];

// ---------------- scratch ----------------
__device__ __align__(16) __half g_encproj16[(size_t)TIN * Bsz * Aa];
__device__ __align__(16) float g_dec[Bsz * Aa];
__device__ __align__(16) float g_scores[TIN * Bsz];
__device__ __align__(16) __half g_x016[Bsz * (2 * Hh + Ee)];
__device__ __align__(16) __half g_xl16[Bsz * 3 * Hh];
__device__ __align__(16) __half g_h16a[Ll * Bsz * Hh];
__device__ __align__(16) __half g_h16b[Ll * Bsz * Hh];
__device__ __align__(16) float g_c[Ll * Bsz * Hh];
__device__ __align__(16) __half g_out16[Bsz * Hh];
__device__ __align__(16) float g_rec[Ll * Bsz * 4 * Hh];
__device__ __align__(16) float g_logits[(size_t)Bsz * Vv];
__device__ unsigned long long g_maxpack[Bsz];
__device__ float g_psum[Bsz * NSEG];
__device__ int g_tok[Bsz];
__device__ int g_barc;
__device__ int g_barp;

// ---------------- helpers ----------------
__device__ __forceinline__ uint32_t pack2(float lo, float hi)
{
    __half2 h = __floats2half2_rn(lo, hi);
    return *(uint32_t*)&h;
}
__device__ __forceinline__ void cp16(uint32_t dst, const void* src)
{
    asm volatile("cp.async.cg.shared.global [%0], [%1], 16;\n" :: "r"(dst), "l"(src));
}
__device__ __forceinline__ void cpcommit() { asm volatile("cp.async.commit_group;\n"); }
template <int N>
__device__ __forceinline__ void cpwait() { asm volatile("cp.async.wait_group %0;\n" :: "n"(N)); }

__device__ __forceinline__ void mma_f16(float* c, const uint32_t* a, const uint32_t* b)
{
    asm volatile(
        "mma.sync.aligned.m16n8k16.row.col.f32.f16.f16.f32 "
        "{%0,%1,%2,%3}, {%4,%5,%6,%7}, {%8,%9}, {%0,%1,%2,%3};"
        : "+f"(c[0]), "+f"(c[1]), "+f"(c[2]), "+f"(c[3])
        : "r"(a[0]), "r"(a[1]), "r"(a[2]), "r"(a[3]), "r"(b[0]), "r"(b[1]));
}
__device__ __forceinline__ float sigmoidf_(float x) { return 1.f / (1.f + expf(-x)); }

// sense-reversing grid barrier (all blocks co-resident). State self-resets.
template <int NBLK>
__device__ __forceinline__ void grid_barrier()
{
    __syncthreads();
    if (threadIdx.x == 0) {
        int p = *(volatile int*)&g_barp;
        __threadfence();
        int old = atomicAdd(&g_barc, 1);
        if (old == NBLK - 1) {
            *(volatile int*)&g_barc = 0;
            __threadfence();
            *(volatile int*)&g_barp = p ^ 1;
        } else {
            while (*(volatile int*)&g_barp == p) {}
        }
        __threadfence();
    }
    __syncthreads();
}

// ---------------- weight packing (vectorized) ----------------
__global__ void pack_plain4_kernel(const float* __restrict__ in, uint32_t* __restrict__ out, int N)
{
    const int k2 = blockIdx.y;
    const int n4 = blockIdx.x * 256 + threadIdx.x;
    if (n4 * 4 < N) {
        float4 lo = *(const float4*)(in + (size_t)(2 * k2) * N + n4 * 4);
        float4 hi = *(const float4*)(in + (size_t)(2 * k2 + 1) * N + n4 * 4);
        uint4 o;
        o.x = pack2(lo.x, hi.x);
        o.y = pack2(lo.y, hi.y);
        o.z = pack2(lo.z, hi.z);
        o.w = pack2(lo.w, hi.w);
        *(uint4*)(out + (size_t)k2 * N + n4 * 4) = o;
    }
}

// gated pack for the NT=4 GEMM layout, 2 columns per thread:
// packed col p: bx=p>>7, c=p&127, gate=(c>>3)&3, orig = gate*Hh + bx*32 + ((c>>5)<<3) + (c&7)
__global__ void pack_gated2_kernel(const float* __restrict__ in, uint32_t* __restrict__ out,
                                   long inStride, long outStride)
{
    in += blockIdx.z * inStride;
    out += blockIdx.z * outStride;
    const int k2 = blockIdx.y;
    const int p = (blockIdx.x * 256 + threadIdx.x) * 2;
    const int c = p & 127, bx = p >> 7;
    const int orig = ((c >> 3) & 3) * Hh + bx * 32 + ((c >> 5) << 3) + (c & 7);
    float2 r0 = *(const float2*)(in + (size_t)(2 * k2) * 4 * Hh + orig);
    float2 r1 = *(const float2*)(in + (size_t)(2 * k2 + 1) * 4 * Hh + orig);
    uint2 o;
    o.x = pack2(r0.x, r1.x);
    o.y = pack2(r0.y, r1.y);
    *(uint2*)(out + (size_t)k2 * 4 * Hh + p) = o;
}

__global__ void cvt_half8_kernel(const float* __restrict__ in, __half* __restrict__ out, size_t n8)
{
    for (size_t i = (size_t)blockIdx.x * blockDim.x + threadIdx.x; i < n8;
         i += (size_t)gridDim.x * blockDim.x) {
        float4 a = ((const float4*)in)[2 * i];
        float4 b = ((const float4*)in)[2 * i + 1];
        uint4 o;
        o.x = pack2(a.x, a.y);
        o.y = pack2(a.z, a.w);
        o.z = pack2(b.x, b.y);
        o.w = pack2(b.z, b.w);
        ((uint4*)out)[i] = o;
    }
}

// ---------------- init (also gathers step-0 embedding: emb[eos]) ----------------
__global__ void init_state_kernel(const float* __restrict__ h0,
                                  const float* __restrict__ c0,
                                  const float* __restrict__ o0,
                                  const int* __restrict__ eos)
{
    int idx = blockIdx.x * blockDim.x + threadIdx.x;
    if (idx < Ll * Bsz * Hh) { g_h16a[idx] = __float2half(h0[idx]); g_c[idx] = c0[idx]; }
    if (idx < Bsz * Hh) g_out16[idx] = __float2half(o0[idx]);
    if (idx < Bsz) { g_tok[idx] = eos[0]; g_maxpack[idx] = 0ull; }
    if (idx == 0) { g_barc = 0; g_barp = 0; }
    if (idx < Bsz * Ee) {
        int b = idx >> 9, e = idx & (Ee - 1);
        g_x016[b * (2 * Hh + Ee) + 2 * Hh + e] = g_emb16[(size_t)eos[0] * Ee + e];
    }
}

// ---------------- pipelined fp16 GEMM (3-stage; MT = 16-row M tiles per block) ----------------
// Tile (MT*16) x (NT*32), 128 threads (4 warps).
// MODE 0: fp32 C (+bias). MODE 1: relu fp32 C + fused argmax. MODE 3: fp16 C.
// DR=1: blockIdx.z==Ll runs the alternate (dec) GEMM from Ax/Bx/Cx.
template <int MODE, int NT, int MT, int DR>
__global__ void __launch_bounds__(128) gemmh_kernel(
    const uint32_t* __restrict__ A, int ldaU, long zsA,
    const uint32_t* __restrict__ Bp, long zsB, int Nu,
    const float* __restrict__ bias,
    float* __restrict__ C, __half* __restrict__ Ch, int ldc, long zsC,
    int K,
    unsigned long long* __restrict__ maxpack,
    const uint32_t* __restrict__ Ax, const uint32_t* __restrict__ Bx,
    float* __restrict__ Cx, const float* __restrict__ biasx, int Nx, int ldcx)
{
    constexpr int BNX = NT * 32;
    constexpr int BSTU = BNX + 8;
    constexpr int BMR = MT * 16;
    constexpr int ASZ = BMR * ASTU;
    constexpr int STAGEU = ASZ + KU * BSTU;
    constexpr int CPR = BNX / 4;

    extern __shared__ uint32_t smu[];
    __shared__ unsigned long long s_max[64];

    if (DR && blockIdx.z == Ll) {
        if (blockIdx.x * BNX >= Nx) return;
        A = Ax; Bp = Bx; C = Cx; bias = biasx; Nu = Nx; ldc = ldcx;
    } else {
        A += blockIdx.z * zsA;
        Bp += blockIdx.z * zsB;
        if ((MODE == 0 || MODE == 1) && C) C += blockIdx.z * zsC;
    }

    const int tid = threadIdx.x;
    const int lane = tid & 31;
    const int w = tid >> 5;
    const int M0 = blockIdx.y * BMR;
    const int bx = blockIdx.x;

    if (MODE == 1 && tid < 64) s_max[tid] = 0ull;

    const uint32_t smb = (uint32_t)__cvta_generic_to_shared(smu);
    const int nch = K / BK;

    auto issue = [&](int c, int s) {
        uint32_t sa = smb + (uint32_t)s * (STAGEU * 4);
        uint32_t sb = sa + ASZ * 4;
        int k20 = c * KU;
#pragma unroll
        for (int i = 0; i < MT / 2; i++) {
            int cid = tid + i * 128;
            int row = cid >> 2, kq = (cid & 3) << 2;
            cp16(sa + (uint32_t)(row * ASTU + kq) * 4,
                 A + (size_t)(M0 + row) * ldaU + k20 + kq);
        }
#pragma unroll
        for (int i = 0; i < NT; i++) {
            int cid = tid + i * 128;
            int kr = cid / CPR, nq = (cid % CPR) << 2;
            cp16(sb + (uint32_t)(kr * BSTU + nq) * 4,
                 Bp + (size_t)(k20 + kr) * Nu + bx * BNX + nq);
        }
        cpcommit();
    };

    float acc[MT][NT][4];
#pragma unroll
    for (int mt = 0; mt < MT; mt++)
#pragma unroll
        for (int t = 0; t < NT; t++)
#pragma unroll
            for (int j = 0; j < 4; j++) acc[mt][t][j] = 0.f;

    issue(0, 0);
    if (nch > 1) issue(1, 1); else cpcommit();

    for (int c = 0; c < nch; c++) {
        cpwait<1>();
        __syncthreads();
        if (c + 2 < nch) issue(c + 2, (c + 2) % NSTAGE); else cpcommit();

        const uint32_t* uA = smu + (c % NSTAGE) * STAGEU;
        const uint32_t* uB = uA + ASZ;
#pragma unroll
        for (int ks = 0; ks < 2; ks++) {
            uint32_t af[MT][4];
            const int ac = ks * 8 + (lane & 3);
            const int ar = lane >> 2;
#pragma unroll
            for (int mt = 0; mt < MT; mt++) {
                const uint32_t* p = uA + (mt * 16 + ar) * ASTU + ac;
                af[mt][0] = p[0];
                af[mt][1] = p[8 * ASTU];
                af[mt][2] = p[4];
                af[mt][3] = p[8 * ASTU + 4];
            }
            uint32_t bf[NT][2];
            const int bk = ks * 8 + (lane & 3);
            const int bn = w * (NT * 8) + (lane >> 2);
#pragma unroll
            for (int t = 0; t < NT; t++) {
                bf[t][0] = uB[bk * BSTU + bn + t * 8];
                bf[t][1] = uB[(bk + 4) * BSTU + bn + t * 8];
            }
#pragma unroll
            for (int mt = 0; mt < MT; mt++)
#pragma unroll
                for (int t = 0; t < NT; t++)
                    mma_f16(acc[mt][t], af[mt], bf[t]);
        }
        __syncthreads();
    }

    const int r0 = lane >> 2;
    const int cb = (lane & 3) * 2;
#pragma unroll
    for (int mt = 0; mt < MT; mt++) {
        int ra = M0 + mt * 16 + r0;
#pragma unroll
        for (int jr = 0; jr < 2; jr++) {
            unsigned long long best = 0ull;
#pragma unroll
            for (int t = 0; t < NT; t++) {
                int col = bx * BNX + w * (NT * 8) + t * 8 + cb;
                float b0 = bias ? bias[col] : 0.f;
                float b1 = bias ? bias[col + 1] : 0.f;
                float v0 = acc[mt][t][jr * 2 + 0] + b0;
                float v1 = acc[mt][t][jr * 2 + 1] + b1;
                if (MODE == 1) {
                    v0 = fmaxf(v0, 0.f);
                    v1 = fmaxf(v1, 0.f);
                    unsigned long long p0 =
                        ((unsigned long long)__float_as_uint(v0) << 32) | (uint32_t)(~col);
                    unsigned long long p1 =
                        ((unsigned long long)__float_as_uint(v1) << 32) | (uint32_t)(~(col + 1));
                    if (p0 > best) best = p0;
                    if (p1 > best) best = p1;
                }
                int row = ra + jr * 8;
                if (MODE == 3) {
                    *(__half2*)&Ch[(size_t)row * ldc + col] = __floats2half2_rn(v0, v1);
                } else {
                    *(float2*)&C[(size_t)row * ldc + col] = make_float2(v0, v1);
                }
            }
            if (MODE == 1)
                atomicMax(&s_max[ra + jr * 8], best);
        }
    }
    if (MODE == 1) {
        __syncthreads();
        if (tid < 64) atomicMax(&maxpack[tid], s_max[tid]);
    }
}

// ---------------- persistent fused LSTM: 64 blocks (M split 2 x 32 rows) ----------------
__global__ void __launch_bounds__(128) lstm_fused_kernel(
    const uint32_t* __restrict__ x0, const uint32_t* __restrict__ Wih0,
    const uint32_t* __restrict__ Wihr,
    const float* __restrict__ rec,
    const float* __restrict__ bihA, const float* __restrict__ bhhA,
    float* __restrict__ cellA, __half* __restrict__ hnewA)
{
    constexpr int NT = 4;
    constexpr int BNX = 128;
    constexpr int BSTU = BNX + 8;
    constexpr int MR = 32;
    constexpr int ASZU32 = MR * ASTU;
    constexpr int STAGEU = ASZU32 + KU * BSTU;
    constexpr int CPR = BNX / 4;

    extern __shared__ uint32_t smu[];
    const int tid = threadIdx.x;
    const int lane = tid & 31;
    const int w = tid >> 5;
    const int bx = blockIdx.x & 31;
    const int M0 = (blockIdx.x >> 5) * MR;
    const uint32_t smb = (uint32_t)__cvta_generic_to_shared(smu);

    for (int l = 0; l < Ll; l++) {
        const uint32_t* A = (l == 0) ? x0
                          : (const uint32_t*)(hnewA + (size_t)(l - 1) * Bsz * Hh);
        const int ldaU = (l == 0) ? (2 * Hh + Ee) / 2 : Hh / 2;
        const int K = (l == 0) ? (2 * Hh + Ee) : Hh;
        const uint32_t* Bp = (l == 0) ? Wih0 : (Wihr + (size_t)(l - 1) * (Hh / 2) * 4 * Hh);
        const float* recl = rec + (size_t)l * Bsz * 4 * Hh;
        const float* bih = bihA + (size_t)l * 4 * Hh;
        const float* bhh = bhhA + (size_t)l * 4 * Hh;
        float* cell = cellA + (size_t)l * Bsz * Hh;
        __half* hout = hnewA + (size_t)l * Bsz * Hh;
        const int nch = K / BK;

        auto issue = [&](int c, int s) {
            uint32_t sa = smb + (uint32_t)s * (STAGEU * 4);
            uint32_t sb = sa + ASZU32 * 4;
            int k20 = c * KU;
            {
                int row = tid >> 2, kq = (tid & 3) << 2;
                cp16(sa + (uint32_t)(row * ASTU + kq) * 4,
                     A + (size_t)(M0 + row) * ldaU + k20 + kq);
            }
#pragma unroll
            for (int i = 0; i < NT; i++) {
                int cid = tid + i * 128;
                int kr = cid / CPR, nq = (cid % CPR) << 2;
                cp16(sb + (uint32_t)(kr * BSTU + nq) * 4,
                     Bp + (size_t)(k20 + kr) * (4 * Hh) + bx * BNX + nq);
            }
            cpcommit();
        };

        float acc[2][NT][4];
#pragma unroll
        for (int mt = 0; mt < 2; mt++)
#pragma unroll
            for (int t = 0; t < NT; t++)
#pragma unroll
                for (int j = 0; j < 4; j++) acc[mt][t][j] = 0.f;

        issue(0, 0);
        if (nch > 1) issue(1, 1); else cpcommit();

        for (int c = 0; c < nch; c++) {
            cpwait<1>();
            __syncthreads();
            if (c + 2 < nch) issue(c + 2, (c + 2) % NSTAGE); else cpcommit();

            const uint32_t* uA = smu + (c % NSTAGE) * STAGEU;
            const uint32_t* uB = uA + ASZU32;
#pragma unroll
            for (int ks = 0; ks < 2; ks++) {
                uint32_t af[2][4];
                const int ac = ks * 8 + (lane & 3);
                const int ar = lane >> 2;
#pragma unroll
                for (int mt = 0; mt < 2; mt++) {
                    const uint32_t* p = uA + (mt * 16 + ar) * ASTU + ac;
                    af[mt][0] = p[0];
                    af[mt][1] = p[8 * ASTU];
                    af[mt][2] = p[4];
                    af[mt][3] = p[8 * ASTU + 4];
                }
                uint32_t bf[NT][2];
                const int bk = ks * 8 + (lane & 3);
                const int bn = w * (NT * 8) + (lane >> 2);
#pragma unroll
                for (int t = 0; t < NT; t++) {
                    bf[t][0] = uB[bk * BSTU + bn + t * 8];
                    bf[t][1] = uB[(bk + 4) * BSTU + bn + t * 8];
                }
#pragma unroll
                for (int mt = 0; mt < 2; mt++)
#pragma unroll
                    for (int t = 0; t < NT; t++)
                        mma_f16(acc[mt][t], af[mt], bf[t]);
            }
            __syncthreads();
        }

        const int r0 = lane >> 2;
        const int cb = (lane & 3) * 2;
#pragma unroll
        for (int mt = 0; mt < 2; mt++)
#pragma unroll
            for (int j = 0; j < 4; j++) {
                int row = M0 + mt * 16 + r0 + (j >> 1) * 8;
                int u = cb + (j & 1);
                int hid = bx * 32 + w * 8 + u;
                int recb = row * (4 * Hh) + bx * 128 + w * 32 + u;
                float xi = acc[mt][0][j] + recl[recb + 0]  + bih[hid]          + bhh[hid];
                float xf = acc[mt][1][j] + recl[recb + 8]  + bih[Hh + hid]     + bhh[Hh + hid];
                float xg = acc[mt][2][j] + recl[recb + 16] + bih[2 * Hh + hid] + bhh[2 * Hh + hid];
                float xo = acc[mt][3][j] + recl[recb + 24] + bih[3 * Hh + hid] + bhh[3 * Hh + hid];
                float iv = sigmoidf_(xi);
                float fv = sigmoidf_(xf);
                float gv = tanhf(xg);
                float ov = sigmoidf_(xo);
                size_t off = (size_t)row * Hh + hid;
                float cn = fv * cell[off] + iv * gv;
                float hn = ov * tanhf(cn);
                cell[off] = cn;
                hout[off] = __float2half(hn);
                if (l == Ll - 1) {
                    g_out16[off] = __float2half(hn);
                    g_xl16[(size_t)row * 3 * Hh + hid] = __float2half(hn);
                }
            }

        if (l < Ll - 1) {
            cpwait<0>();
            grid_barrier<64>();
        }
    }
}

// ---------------- attention scores ----------------
__global__ __launch_bounds__(128) void attn_scores_kernel(
    const float* __restrict__ is_on,
    const float* __restrict__ A2, const float* __restrict__ b2)
{
    const int t = blockIdx.x, b = blockIdx.y;
    const int tid = threadIdx.x;
    const __half2* ep = (const __half2*)(g_encproj16 + ((size_t)t * Bsz + b) * Aa);
    float2 e0 = __half22float2(ep[2 * tid]);
    float2 e1 = __half22float2(ep[2 * tid + 1]);
    const float4 d = ((const float4*)(g_dec + b * Aa))[tid];
    const float4 a = ((const float4*)A2)[tid];
    float s = tanhf(e0.x + d.x) * a.x + tanhf(e0.y + d.y) * a.y +
              tanhf(e1.x + d.z) * a.z + tanhf(e1.y + d.w) * a.w;
#pragma unroll
    for (int o = 16; o > 0; o >>= 1) s += __shfl_down_sync(0xffffffffu, s, o);
    __shared__ float ws[4];
    if ((tid & 31) == 0) ws[tid >> 5] = s;
    __syncthreads();
    if (tid == 0) {
        float tot = ws[0] + ws[1] + ws[2] + ws[3];
        g_scores[t * Bsz + b] = tot + b2[0] + (1.f - is_on[t * Bsz + b]) * (-1e30f);
    }
}

// ---------------- softmax over T + context ----------------
__global__ __launch_bounds__(256) void attn_context_kernel()
{
    const int b = blockIdx.x;
    const int dchunk = blockIdx.y;
    const int tid = threadIdx.x;
    __shared__ float sAlpha[TIN];
    __shared__ float red[256];

    float v = (tid < TIN) ? g_scores[tid * Bsz + b] : -3.4e38f;
    red[tid] = v;
    __syncthreads();
    for (int st = 128; st > 0; st >>= 1) {
        if (tid < st) red[tid] = fmaxf(red[tid], red[tid + st]);
        __syncthreads();
    }
    float mx = red[0];
    __syncthreads();
    float e = (tid < TIN) ? expf(v - mx) : 0.f;
    if (tid < TIN) sAlpha[tid] = e;
    red[tid] = e;
    __syncthreads();
    for (int st = 128; st > 0; st >>= 1) {
        if (tid < st) red[tid] += red[tid + st];
        __syncthreads();
    }
    float inv = 1.f / red[0];

    const int d = dchunk * 256 + tid;
    const __half* ep = g_enc16 + (size_t)b * (2 * Hh) + d;
    float acc = 0.f;
#pragma unroll 4
    for (int t = 0; t < TIN; t++)
        acc += sAlpha[t] * __half2float(ep[(size_t)t * Bsz * 2 * Hh]);
    __half ctx = __float2half(acc * inv);
    g_x016[b * (2 * Hh + Ee) + d] = ctx;
    g_xl16[b * 3 * Hh + Hh + d] = ctx;
}

// ---------------- wide softmax-V: exp + partial sums (+token/emb on seg 0) ----------------
__global__ __launch_bounds__(256) void smax_exp_kernel(float* __restrict__ outp)
{
    const int b = blockIdx.x, s = blockIdx.y;
    const int tid = threadIdx.x;

    unsigned long long pk = g_maxpack[b];
    float gmax = __uint_as_float((uint32_t)(pk >> 32));

    if (s == 0) {
        int tok = (int)(~(uint32_t)(pk & 0xFFFFFFFFull));
        if (tid == 0) g_tok[b] = tok;
        const __half* er = g_emb16 + (size_t)tok * Ee;
        g_x016[b * (2 * Hh + Ee) + 2 * Hh + tid] = er[tid];
        g_x016[b * (2 * Hh + Ee) + 2 * Hh + tid + 256] = er[tid + 256];
    }

    const float4* lr4 = (const float4*)(g_logits + (size_t)b * Vv + s * SEGV);
    float4* o4 = (float4*)(outp + (size_t)b * Vv + s * SEGV);
    float sum = 0.f;
    for (int i = tid; i < SEGV / 4; i += 256) {
        float4 x = lr4[i];
        float4 e = make_float4(expf(x.x - gmax), expf(x.y - gmax),
                               expf(x.z - gmax), expf(x.w - gmax));
        o4[i] = e;
        sum += e.x + e.y + e.z + e.w;
    }
    __shared__ float rv[256];
    rv[tid] = sum;
    __syncthreads();
    for (int st = 128; st > 0; st >>= 1) {
        if (tid < st) rv[tid] += rv[tid + st];
        __syncthreads();
    }
    if (tid == 0) g_psum[b * NSEG + s] = rv[0];
}

// ---------------- wide softmax-V: rescale (+maxpack reset) ----------------
__global__ __launch_bounds__(256) void smax_scale_kernel(float* __restrict__ outp)
{
    const int b = blockIdx.x, s = blockIdx.y;
    const int tid = threadIdx.x;
    float tot = 0.f;
#pragma unroll
    for (int k = 0; k < NSEG; k++) tot += g_psum[b * NSEG + k];
    const float inv = 1.f / tot;
    if (s == 0 && tid == 0) g_maxpack[b] = 0ull;
    float4* o4 = (float4*)(outp + (size_t)b * Vv + s * SEGV);
    for (int i = tid; i < SEGV / 4; i += 256) {
        float4 e = o4[i];
        o4[i] = make_float4(e.x * inv, e.y * inv, e.z * inv, e.w * inv);
    }
}

// ---------------- host orchestration ----------------
extern "C" void kernel_launch(void* const* d_in, const int* in_sizes, int n_in,
                              void* d_out, int out_size)
{
    const float* enc   = (const float*)d_in[0];
    const float* is_on = (const float*)d_in[1];
    const float* emb   = (const float*)d_in[2];
    const float* A1    = (const float*)d_in[3];
    const float* b1    = (const float*)d_in[4];
    const float* A2    = (const float*)d_in[5];
    const float* b2    = (const float*)d_in[6];
    const float* W_ih0 = (const float*)d_in[7];
    const float* W_ihr = (const float*)d_in[8];
    const float* W_hh  = (const float*)d_in[9];
    const float* b_ih  = (const float*)d_in[10];
    const float* b_hh  = (const float*)d_in[11];
    const float* Wl    = (const float*)d_in[12];
    const float* bl    = (const float*)d_in[13];
    const float* h0    = (const float*)d_in[14];
    const float* c0    = (const float*)d_in[15];
    const float* o0    = (const float*)d_in[16];
    const int*   eos   = (const int*)d_in[17];
    float* out = (float*)d_out;

    uint32_t *pWl, *pWih0, *pWihr, *pWhh, *pA1lo, *pA1hi;
    __half *pEmb16, *pEnc16, *pEncproj16, *pX016, *pXl16, *pHa, *pHb, *pOut16;
    float *pDec, *pC, *pRec, *pLogits;
    unsigned long long* pMaxpack;
    cudaGetSymbolAddress((void**)&pWl, g_Wl16);
    cudaGetSymbolAddress((void**)&pWih0, g_Wih016);
    cudaGetSymbolAddress((void**)&pWihr, g_Wihr16);
    cudaGetSymbolAddress((void**)&pWhh, g_Whh16);
    cudaGetSymbolAddress((void**)&pA1lo, g_A1lo16);
    cudaGetSymbolAddress((void**)&pA1hi, g_A1hi16);
    cudaGetSymbolAddress((void**)&pEmb16, g_emb16);
    cudaGetSymbolAddress((void**)&pEnc16, g_enc16);
    cudaGetSymbolAddress((void**)&pEncproj16, g_encproj16);
    cudaGetSymbolAddress((void**)&pX016, g_x016);
    cudaGetSymbolAddress((void**)&pXl16, g_xl16);
    cudaGetSymbolAddress((void**)&pHa, g_h16a);
    cudaGetSymbolAddress((void**)&pHb, g_h16b);
    cudaGetSymbolAddress((void**)&pOut16, g_out16);
    cudaGetSymbolAddress((void**)&pDec, g_dec);
    cudaGetSymbolAddress((void**)&pC, g_c);
    cudaGetSymbolAddress((void**)&pRec, g_rec);
    cudaGetSymbolAddress((void**)&pLogits, g_logits);
    cudaGetSymbolAddress((void**)&pMaxpack, g_maxpack);

    // smem sizes (3-stage)
    const int SM8_MT4 = (64 * ASTU + KU * (256 + 8)) * 4 * 3;   // 66048 (encproj)
    const int SM8_MT2 = (32 * ASTU + KU * (256 + 8)) * 4 * 3;   // 58368 (logits M-split)
    const int SM4_MT2 = (32 * ASTU + KU * (128 + 8)) * 4 * 3;   // 33792 (recdec M-split, lstm)
    cudaFuncSetAttribute(gemmh_kernel<3, 8, 4, 0>, cudaFuncAttributeMaxDynamicSharedMemorySize, SM8_MT4);
    cudaFuncSetAttribute(gemmh_kernel<1, 8, 2, 0>, cudaFuncAttributeMaxDynamicSharedMemorySize, SM8_MT2);
    cudaFuncSetAttribute(gemmh_kernel<0, 4, 2, 1>, cudaFuncAttributeMaxDynamicSharedMemorySize, SM4_MT2);
    cudaFuncSetAttribute(lstm_fused_kernel, cudaFuncAttributeMaxDynamicSharedMemorySize, SM4_MT2);

    // ---- per-launch weight packing (vectorized) ----
    pack_plain4_kernel<<<dim3(32, 3 * Hh / 2), 256>>>(Wl, pWl, Vv);
    pack_plain4_kernel<<<dim3(1, Hh / 2), 256>>>(A1, pA1lo, Aa);
    pack_plain4_kernel<<<dim3(1, Hh), 256>>>(A1 + (size_t)Hh * Aa, pA1hi, Aa);
    pack_gated2_kernel<<<dim3(8, (2 * Hh + Ee) / 2, 1), 256>>>(W_ih0, pWih0, 0, 0);
    pack_gated2_kernel<<<dim3(8, Hh / 2, 3), 256>>>(W_ihr, pWihr,
        (long)Hh * 4 * Hh, (long)(Hh / 2) * 4 * Hh);
    pack_gated2_kernel<<<dim3(8, Hh / 2, Ll), 256>>>(W_hh, pWhh,
        (long)Hh * 4 * Hh, (long)(Hh / 2) * 4 * Hh);
    cvt_half8_kernel<<<2048, 256>>>(emb, pEmb16, (size_t)Vv * Ee / 8);
    cvt_half8_kernel<<<2048, 256>>>(enc, pEnc16, (size_t)TIN * Bsz * 2 * Hh / 8);

    init_state_kernel<<<(Ll * Bsz * Hh + 255) / 256, 256>>>(h0, c0, o0, eos);

    // enc_proj = enc @ A1[H:]  (8192x512, K=2048) -> fp16 (MT=4)
    gemmh_kernel<3, 8, 4, 0><<<dim3(2, 128), 128, SM8_MT4>>>(
        (const uint32_t*)pEnc16, Hh, 0, pA1hi, 0, Aa,
        nullptr, nullptr, pEncproj16, Aa, 0, 2 * Hh,
        nullptr, nullptr, nullptr, nullptr, nullptr, 0, 0);

    for (int s = 0; s < TOUT; s++) {
        __half* hold = (s & 1) ? pHb : pHa;
        __half* hnew = (s & 1) ? pHa : pHb;

        // merged rec+dec, M split 2x32: 320 blocks
        gemmh_kernel<0, 4, 2, 1><<<dim3(32, 2, Ll + 1), 128, SM4_MT2>>>(
            (const uint32_t*)hold, Hh / 2, (long)Bsz * Hh / 2,
            pWhh, (long)(Hh / 2) * 4 * Hh, 4 * Hh,
            nullptr, pRec, nullptr, 4 * Hh, (long)Bsz * 4 * Hh, Hh,
            nullptr,
            (const uint32_t*)pOut16, pA1lo, pDec, b1, Aa, Aa);

        attn_scores_kernel<<<dim3(TIN, Bsz), 128>>>(is_on, A2, b2);
        attn_context_kernel<<<dim3(Bsz, (2 * Hh) / 256), 256>>>();

        // persistent fused LSTM (64 blocks, M split 2x32)
        lstm_fused_kernel<<<64, 128, SM4_MT2>>>(
            (const uint32_t*)pX016, pWih0, pWihr,
            pRec, b_ih, b_hh, pC, hnew);

        // logits + fused argmax, M split 2x32: 250 blocks
        gemmh_kernel<1, 8, 2, 0><<<dim3(Vv / 256, 2), 128, SM8_MT2>>>(
            (const uint32_t*)pXl16, 3 * Hh / 2, 0, pWl, 0, Vv,
            bl, pLogits, nullptr, Vv, 0, 3 * Hh,
            pMaxpack,
            nullptr, nullptr, nullptr, nullptr, 0, 0);

        // wide softmax: exp (+token/emb) then rescale (+maxpack reset)
        smax_exp_kernel<<<dim3(Bsz, NSEG), 256>>>(out + (size_t)s * Bsz * Vv);
        smax_scale_kernel<<<dim3(Bsz, NSEG), 256>>>(out + (size_t)s * Bsz * Vv);
    }
    (void)in_sizes; (void)n_in; (void)out_size;
}

// round 17
// speedup vs baseline: 1.0528x; 1.0528x over previous
#include <cuda_runtime.h>
#include <cuda_fp16.h>
#include <math.h>
#include <stdint.h>

#define Bsz 64
#define TIN 128
#define TOUT 32
#define Vv 32000
#define Ee 512
#define Hh 1024
#define Aa 512
#define Ll 4
#define NSEG 8
#define SEGV (Vv / NSEG)

// GEMM tiling (fp16, k-paired u32 domain)
#define BM 64
#define BK 32                   // halves per K-chunk
#define KU (BK / 2)             // 16 u32 rows per chunk
#define ASTU 20                 // A smem row stride (u32, pad 4)
#define ASZU (BM * ASTU)        // 1280 u32
#define NSTAGE 3

// ---------------- fp16 packed weights (filled per launch) ----------------
__device__ __align__(16) uint32_t g_Wl16[(size_t)(3 * Hh / 2) * Vv];
__device__ __align__(16) uint32_t g_Wih016[(2 * Hh + Ee) / 2 * 4 * Hh];
__device__ __align__(16) uint32_t g_Wihr16[3][(Hh / 2) * 4 * Hh];
__device__ __align__(16) uint32_t g_Whh16[Ll][(Hh / 2) * 4 * Hh];
__device__ __align__(16) uint32_t g_A1lo16[(Hh / 2) * Aa];
__device__ __align__(16) uint32_t g_A1hi16[Hh * Aa];
__device__ __align__(16) __half g_emb16[(size_t)Vv * Ee];
__device__ __align__(16) __half g_enc16[(size_t)TIN * Bsz * 2 * Hh];

// ---------------- scratch ----------------
__device__ __align__(16) __half g_encproj16[(size_t)TIN * Bsz * Aa];
__device__ __align__(16) float g_dec[Bsz * Aa];
__device__ __align__(16) float g_scores[TIN * Bsz];
__device__ __align__(16) __half g_x016[Bsz * (2 * Hh + Ee)];
__device__ __align__(16) __half g_xl16[Bsz * 3 * Hh];
__device__ __align__(16) __half g_h16a[Ll * Bsz * Hh];
__device__ __align__(16) __half g_h16b[Ll * Bsz * Hh];
__device__ __align__(16) float g_c[Ll * Bsz * Hh];
__device__ __align__(16) __half g_out16[Bsz * Hh];
__device__ __align__(16) float g_rec[Ll * Bsz * 4 * Hh];
__device__ __align__(16) float g_logits[(size_t)Bsz * Vv];
__device__ unsigned long long g_maxpack[Bsz];
__device__ float g_psum[Bsz * NSEG];
__device__ int g_tok[Bsz];
__device__ int g_barc;
__device__ int g_barp;

// ---------------- helpers ----------------
__device__ __forceinline__ uint32_t pack2(float lo, float hi)
{
    __half2 h = __floats2half2_rn(lo, hi);
    return *(uint32_t*)&h;
}
__device__ __forceinline__ void cp16(uint32_t dst, const void* src)
{
    asm volatile("cp.async.cg.shared.global [%0], [%1], 16;\n" :: "r"(dst), "l"(src));
}
__device__ __forceinline__ void cpcommit() { asm volatile("cp.async.commit_group;\n"); }
template <int N>
__device__ __forceinline__ void cpwait() { asm volatile("cp.async.wait_group %0;\n" :: "n"(N)); }

__device__ __forceinline__ void mma_f16(float* c, const uint32_t* a, const uint32_t* b)
{
    asm volatile(
        "mma.sync.aligned.m16n8k16.row.col.f32.f16.f16.f32 "
        "{%0,%1,%2,%3}, {%4,%5,%6,%7}, {%8,%9}, {%0,%1,%2,%3};"
        : "+f"(c[0]), "+f"(c[1]), "+f"(c[2]), "+f"(c[3])
        : "r"(a[0]), "r"(a[1]), "r"(a[2]), "r"(a[3]), "r"(b[0]), "r"(b[1]));
}
__device__ __forceinline__ float sigmoidf_(float x) { return 1.f / (1.f + expf(-x)); }

// sense-reversing grid barrier (all blocks co-resident). State self-resets.
template <int NBLK>
__device__ __forceinline__ void grid_barrier()
{
    __syncthreads();
    if (threadIdx.x == 0) {
        int p = *(volatile int*)&g_barp;
        __threadfence();
        int old = atomicAdd(&g_barc, 1);
        if (old == NBLK - 1) {
            *(volatile int*)&g_barc = 0;
            __threadfence();
            *(volatile int*)&g_barp = p ^ 1;
        } else {
            while (*(volatile int*)&g_barp == p) {}
        }
        __threadfence();
    }
    __syncthreads();
}

// ---------------- weight packing (vectorized) ----------------
__global__ void pack_plain4_kernel(const float* __restrict__ in, uint32_t* __restrict__ out, int N)
{
    const int k2 = blockIdx.y;
    const int n4 = blockIdx.x * 256 + threadIdx.x;
    if (n4 * 4 < N) {
        float4 lo = *(const float4*)(in + (size_t)(2 * k2) * N + n4 * 4);
        float4 hi = *(const float4*)(in + (size_t)(2 * k2 + 1) * N + n4 * 4);
        uint4 o;
        o.x = pack2(lo.x, hi.x);
        o.y = pack2(lo.y, hi.y);
        o.z = pack2(lo.z, hi.z);
        o.w = pack2(lo.w, hi.w);
        *(uint4*)(out + (size_t)k2 * N + n4 * 4) = o;
    }
}

// gated pack for the NT=4 GEMM layout, 2 columns per thread:
// packed col p: bx=p>>7, c=p&127, gate=(c>>3)&3, orig = gate*Hh + bx*32 + ((c>>5)<<3) + (c&7)
__global__ void pack_gated2_kernel(const float* __restrict__ in, uint32_t* __restrict__ out,
                                   long inStride, long outStride)
{
    in += blockIdx.z * inStride;
    out += blockIdx.z * outStride;
    const int k2 = blockIdx.y;
    const int p = (blockIdx.x * 256 + threadIdx.x) * 2;
    const int c = p & 127, bx = p >> 7;
    const int orig = ((c >> 3) & 3) * Hh + bx * 32 + ((c >> 5) << 3) + (c & 7);
    float2 r0 = *(const float2*)(in + (size_t)(2 * k2) * 4 * Hh + orig);
    float2 r1 = *(const float2*)(in + (size_t)(2 * k2 + 1) * 4 * Hh + orig);
    uint2 o;
    o.x = pack2(r0.x, r1.x);
    o.y = pack2(r0.y, r1.y);
    *(uint2*)(out + (size_t)k2 * 4 * Hh + p) = o;
}

__global__ void cvt_half8_kernel(const float* __restrict__ in, __half* __restrict__ out, size_t n8)
{
    for (size_t i = (size_t)blockIdx.x * blockDim.x + threadIdx.x; i < n8;
         i += (size_t)gridDim.x * blockDim.x) {
        float4 a = ((const float4*)in)[2 * i];
        float4 b = ((const float4*)in)[2 * i + 1];
        uint4 o;
        o.x = pack2(a.x, a.y);
        o.y = pack2(a.z, a.w);
        o.z = pack2(b.x, b.y);
        o.w = pack2(b.z, b.w);
        ((uint4*)out)[i] = o;
    }
}

// ---------------- init (also gathers step-0 embedding: emb[eos]) ----------------
__global__ void init_state_kernel(const float* __restrict__ h0,
                                  const float* __restrict__ c0,
                                  const float* __restrict__ o0,
                                  const int* __restrict__ eos)
{
    int idx = blockIdx.x * blockDim.x + threadIdx.x;
    if (idx < Ll * Bsz * Hh) { g_h16a[idx] = __float2half(h0[idx]); g_c[idx] = c0[idx]; }
    if (idx < Bsz * Hh) g_out16[idx] = __float2half(o0[idx]);
    if (idx < Bsz) { g_tok[idx] = eos[0]; g_maxpack[idx] = 0ull; }
    if (idx == 0) { g_barc = 0; g_barp = 0; }
    if (idx < Bsz * Ee) {
        int b = idx >> 9, e = idx & (Ee - 1);
        g_x016[b * (2 * Hh + Ee) + 2 * Hh + e] = g_emb16[(size_t)eos[0] * Ee + e];
    }
}

// ---------------- pipelined fp16 GEMM (3-stage, airtight group accounting) ----------------
// Tile 64 x (NT*32), 128 threads (4 warps, each 64M x NT*8 cols).
// MODE 0: fp32 C (+bias). MODE 1: relu fp32 C + fused argmax. MODE 3: fp16 C.
// DR=1: blockIdx.z==Ll runs the alternate (dec) GEMM from Ax/Bx/Cx.
template <int MODE, int NT, int DR>
__global__ void __launch_bounds__(128) gemmh_kernel(
    const uint32_t* __restrict__ A, int ldaU, long zsA,
    const uint32_t* __restrict__ Bp, long zsB, int Nu,
    const float* __restrict__ bias,
    float* __restrict__ C, __half* __restrict__ Ch, int ldc, long zsC,
    int K,
    unsigned long long* __restrict__ maxpack,
    const uint32_t* __restrict__ Ax, const uint32_t* __restrict__ Bx,
    float* __restrict__ Cx, const float* __restrict__ biasx, int Nx, int ldcx)
{
    constexpr int BNX = NT * 32;
    constexpr int BSTU = BNX + 8;
    constexpr int BSZU = KU * BSTU;
    constexpr int STAGEU = ASZU + BSZU;
    constexpr int CPR = BNX / 4;

    extern __shared__ uint32_t smu[];
    __shared__ unsigned long long s_max[64];

    if (DR && blockIdx.z == Ll) {
        if (blockIdx.x * BNX >= Nx) return;
        A = Ax; Bp = Bx; C = Cx; bias = biasx; Nu = Nx; ldc = ldcx;
    } else {
        A += blockIdx.z * zsA;
        Bp += blockIdx.z * zsB;
        if ((MODE == 0 || MODE == 1) && C) C += blockIdx.z * zsC;
    }

    const int tid = threadIdx.x;
    const int lane = tid & 31;
    const int w = tid >> 5;
    const int M0 = blockIdx.y * BM;
    const int bx = blockIdx.x;

    if (MODE == 1 && tid < 64) s_max[tid] = 0ull;

    const uint32_t smb = (uint32_t)__cvta_generic_to_shared(smu);
    const int nch = K / BK;

    auto issue = [&](int c, int s) {
        uint32_t sa = smb + (uint32_t)s * (STAGEU * 4);
        uint32_t sb = sa + ASZU * 4;
        int k20 = c * KU;
#pragma unroll
        for (int i = 0; i < 2; i++) {
            int cid = tid + i * 128;
            int row = cid >> 2, kq = (cid & 3) << 2;
            cp16(sa + (uint32_t)(row * ASTU + kq) * 4,
                 A + (size_t)(M0 + row) * ldaU + k20 + kq);
        }
#pragma unroll
        for (int i = 0; i < NT; i++) {
            int cid = tid + i * 128;
            int kr = cid / CPR, nq = (cid % CPR) << 2;
            cp16(sb + (uint32_t)(kr * BSTU + nq) * 4,
                 Bp + (size_t)(k20 + kr) * Nu + bx * BNX + nq);
        }
        cpcommit();
    };

    float acc[4][NT][4];
#pragma unroll
    for (int mt = 0; mt < 4; mt++)
#pragma unroll
        for (int t = 0; t < NT; t++)
#pragma unroll
            for (int j = 0; j < 4; j++) acc[mt][t][j] = 0.f;

    issue(0, 0);
    if (nch > 1) issue(1, 1); else cpcommit();

    for (int c = 0; c < nch; c++) {
        cpwait<1>();
        __syncthreads();
        if (c + 2 < nch) issue(c + 2, (c + 2) % NSTAGE); else cpcommit();

        const uint32_t* uA = smu + (c % NSTAGE) * STAGEU;
        const uint32_t* uB = uA + ASZU;
#pragma unroll
        for (int ks = 0; ks < 2; ks++) {
            uint32_t af[4][4];
            const int ac = ks * 8 + (lane & 3);
            const int ar = lane >> 2;
#pragma unroll
            for (int mt = 0; mt < 4; mt++) {
                const uint32_t* p = uA + (mt * 16 + ar) * ASTU + ac;
                af[mt][0] = p[0];
                af[mt][1] = p[8 * ASTU];
                af[mt][2] = p[4];
                af[mt][3] = p[8 * ASTU + 4];
            }
            uint32_t bf[NT][2];
            const int bk = ks * 8 + (lane & 3);
            const int bn = w * (NT * 8) + (lane >> 2);
#pragma unroll
            for (int t = 0; t < NT; t++) {
                bf[t][0] = uB[bk * BSTU + bn + t * 8];
                bf[t][1] = uB[(bk + 4) * BSTU + bn + t * 8];
            }
#pragma unroll
            for (int mt = 0; mt < 4; mt++)
#pragma unroll
                for (int t = 0; t < NT; t++)
                    mma_f16(acc[mt][t], af[mt], bf[t]);
        }
        __syncthreads();
    }

    const int r0 = lane >> 2;
    const int cb = (lane & 3) * 2;
#pragma unroll
    for (int mt = 0; mt < 4; mt++) {
        int ra = M0 + mt * 16 + r0;
#pragma unroll
        for (int jr = 0; jr < 2; jr++) {
            unsigned long long best = 0ull;
#pragma unroll
            for (int t = 0; t < NT; t++) {
                int col = bx * BNX + w * (NT * 8) + t * 8 + cb;
                float b0 = bias ? bias[col] : 0.f;
                float b1 = bias ? bias[col + 1] : 0.f;
                float v0 = acc[mt][t][jr * 2 + 0] + b0;
                float v1 = acc[mt][t][jr * 2 + 1] + b1;
                if (MODE == 1) {
                    v0 = fmaxf(v0, 0.f);
                    v1 = fmaxf(v1, 0.f);
                    unsigned long long p0 =
                        ((unsigned long long)__float_as_uint(v0) << 32) | (uint32_t)(~col);
                    unsigned long long p1 =
                        ((unsigned long long)__float_as_uint(v1) << 32) | (uint32_t)(~(col + 1));
                    if (p0 > best) best = p0;
                    if (p1 > best) best = p1;
                }
                int row = ra + jr * 8;
                if (MODE == 3) {
                    *(__half2*)&Ch[(size_t)row * ldc + col] = __floats2half2_rn(v0, v1);
                } else {
                    *(float2*)&C[(size_t)row * ldc + col] = make_float2(v0, v1);
                }
            }
            if (MODE == 1)
                atomicMax(&s_max[ra + jr * 8], best);
        }
    }
    if (MODE == 1) {
        __syncthreads();
        if (tid < 64) atomicMax(&maxpack[tid], s_max[tid]);
    }
}

// ---------------- persistent fused LSTM: 64 blocks (M split 2 x 32 rows) ----------------
__global__ void __launch_bounds__(128) lstm_fused_kernel(
    const uint32_t* __restrict__ x0, const uint32_t* __restrict__ Wih0,
    const uint32_t* __restrict__ Wihr,
    const float* __restrict__ rec,
    const float* __restrict__ bihA, const float* __restrict__ bhhA,
    float* __restrict__ cellA, __half* __restrict__ hnewA)
{
    constexpr int NT = 4;
    constexpr int BNX = 128;
    constexpr int BSTU = BNX + 8;
    constexpr int MR = 32;
    constexpr int ASZU32 = MR * ASTU;
    constexpr int STAGEU = ASZU32 + KU * BSTU;
    constexpr int CPR = BNX / 4;

    extern __shared__ uint32_t smu[];
    const int tid = threadIdx.x;
    const int lane = tid & 31;
    const int w = tid >> 5;
    const int bx = blockIdx.x & 31;
    const int M0 = (blockIdx.x >> 5) * MR;
    const uint32_t smb = (uint32_t)__cvta_generic_to_shared(smu);

    for (int l = 0; l < Ll; l++) {
        const uint32_t* A = (l == 0) ? x0
                          : (const uint32_t*)(hnewA + (size_t)(l - 1) * Bsz * Hh);
        const int ldaU = (l == 0) ? (2 * Hh + Ee) / 2 : Hh / 2;
        const int K = (l == 0) ? (2 * Hh + Ee) : Hh;
        const uint32_t* Bp = (l == 0) ? Wih0 : (Wihr + (size_t)(l - 1) * (Hh / 2) * 4 * Hh);
        const float* recl = rec + (size_t)l * Bsz * 4 * Hh;
        const float* bih = bihA + (size_t)l * 4 * Hh;
        const float* bhh = bhhA + (size_t)l * 4 * Hh;
        float* cell = cellA + (size_t)l * Bsz * Hh;
        __half* hout = hnewA + (size_t)l * Bsz * Hh;
        const int nch = K / BK;

        auto issue = [&](int c, int s) {
            uint32_t sa = smb + (uint32_t)s * (STAGEU * 4);
            uint32_t sb = sa + ASZU32 * 4;
            int k20 = c * KU;
            {
                int row = tid >> 2, kq = (tid & 3) << 2;
                cp16(sa + (uint32_t)(row * ASTU + kq) * 4,
                     A + (size_t)(M0 + row) * ldaU + k20 + kq);
            }
#pragma unroll
            for (int i = 0; i < NT; i++) {
                int cid = tid + i * 128;
                int kr = cid / CPR, nq = (cid % CPR) << 2;
                cp16(sb + (uint32_t)(kr * BSTU + nq) * 4,
                     Bp + (size_t)(k20 + kr) * (4 * Hh) + bx * BNX + nq);
            }
            cpcommit();
        };

        float acc[2][NT][4];
#pragma unroll
        for (int mt = 0; mt < 2; mt++)
#pragma unroll
            for (int t = 0; t < NT; t++)
#pragma unroll
                for (int j = 0; j < 4; j++) acc[mt][t][j] = 0.f;

        issue(0, 0);
        if (nch > 1) issue(1, 1); else cpcommit();

        for (int c = 0; c < nch; c++) {
            cpwait<1>();
            __syncthreads();
            if (c + 2 < nch) issue(c + 2, (c + 2) % NSTAGE); else cpcommit();

            const uint32_t* uA = smu + (c % NSTAGE) * STAGEU;
            const uint32_t* uB = uA + ASZU32;
#pragma unroll
            for (int ks = 0; ks < 2; ks++) {
                uint32_t af[2][4];
                const int ac = ks * 8 + (lane & 3);
                const int ar = lane >> 2;
#pragma unroll
                for (int mt = 0; mt < 2; mt++) {
                    const uint32_t* p = uA + (mt * 16 + ar) * ASTU + ac;
                    af[mt][0] = p[0];
                    af[mt][1] = p[8 * ASTU];
                    af[mt][2] = p[4];
                    af[mt][3] = p[8 * ASTU + 4];
                }
                uint32_t bf[NT][2];
                const int bk = ks * 8 + (lane & 3);
                const int bn = w * (NT * 8) + (lane >> 2);
#pragma unroll
                for (int t = 0; t < NT; t++) {
                    bf[t][0] = uB[bk * BSTU + bn + t * 8];
                    bf[t][1] = uB[(bk + 4) * BSTU + bn + t * 8];
                }
#pragma unroll
                for (int mt = 0; mt < 2; mt++)
#pragma unroll
                    for (int t = 0; t < NT; t++)
                        mma_f16(acc[mt][t], af[mt], bf[t]);
            }
            __syncthreads();
        }

        const int r0 = lane >> 2;
        const int cb = (lane & 3) * 2;
#pragma unroll
        for (int mt = 0; mt < 2; mt++)
#pragma unroll
            for (int j = 0; j < 4; j++) {
                int row = M0 + mt * 16 + r0 + (j >> 1) * 8;
                int u = cb + (j & 1);
                int hid = bx * 32 + w * 8 + u;
                int recb = row * (4 * Hh) + bx * 128 + w * 32 + u;
                float xi = acc[mt][0][j] + recl[recb + 0]  + bih[hid]          + bhh[hid];
                float xf = acc[mt][1][j] + recl[recb + 8]  + bih[Hh + hid]     + bhh[Hh + hid];
                float xg = acc[mt][2][j] + recl[recb + 16] + bih[2 * Hh + hid] + bhh[2 * Hh + hid];
                float xo = acc[mt][3][j] + recl[recb + 24] + bih[3 * Hh + hid] + bhh[3 * Hh + hid];
                float iv = sigmoidf_(xi);
                float fv = sigmoidf_(xf);
                float gv = tanhf(xg);
                float ov = sigmoidf_(xo);
                size_t off = (size_t)row * Hh + hid;
                float cn = fv * cell[off] + iv * gv;
                float hn = ov * tanhf(cn);
                cell[off] = cn;
                hout[off] = __float2half(hn);
                if (l == Ll - 1) {
                    g_out16[off] = __float2half(hn);
                    g_xl16[(size_t)row * 3 * Hh + hid] = __float2half(hn);
                }
            }

        if (l < Ll - 1) {
            cpwait<0>();
            grid_barrier<64>();
        }
    }
}

// ---------------- attention scores ----------------
__global__ __launch_bounds__(128) void attn_scores_kernel(
    const float* __restrict__ is_on,
    const float* __restrict__ A2, const float* __restrict__ b2)
{
    const int t = blockIdx.x, b = blockIdx.y;
    const int tid = threadIdx.x;
    const __half2* ep = (const __half2*)(g_encproj16 + ((size_t)t * Bsz + b) * Aa);
    float2 e0 = __half22float2(ep[2 * tid]);
    float2 e1 = __half22float2(ep[2 * tid + 1]);
    const float4 d = ((const float4*)(g_dec + b * Aa))[tid];
    const float4 a = ((const float4*)A2)[tid];
    float s = tanhf(e0.x + d.x) * a.x + tanhf(e0.y + d.y) * a.y +
              tanhf(e1.x + d.z) * a.z + tanhf(e1.y + d.w) * a.w;
#pragma unroll
    for (int o = 16; o > 0; o >>= 1) s += __shfl_down_sync(0xffffffffu, s, o);
    __shared__ float ws[4];
    if ((tid & 31) == 0) ws[tid >> 5] = s;
    __syncthreads();
    if (tid == 0) {
        float tot = ws[0] + ws[1] + ws[2] + ws[3];
        g_scores[t * Bsz + b] = tot + b2[0] + (1.f - is_on[t * Bsz + b]) * (-1e30f);
    }
}

// ---------------- softmax over T + context ----------------
__global__ __launch_bounds__(256) void attn_context_kernel()
{
    const int b = blockIdx.x;
    const int dchunk = blockIdx.y;
    const int tid = threadIdx.x;
    __shared__ float sAlpha[TIN];
    __shared__ float red[256];

    float v = (tid < TIN) ? g_scores[tid * Bsz + b] : -3.4e38f;
    red[tid] = v;
    __syncthreads();
    for (int st = 128; st > 0; st >>= 1) {
        if (tid < st) red[tid] = fmaxf(red[tid], red[tid + st]);
        __syncthreads();
    }
    float mx = red[0];
    __syncthreads();
    float e = (tid < TIN) ? expf(v - mx) : 0.f;
    if (tid < TIN) sAlpha[tid] = e;
    red[tid] = e;
    __syncthreads();
    for (int st = 128; st > 0; st >>= 1) {
        if (tid < st) red[tid] += red[tid + st];
        __syncthreads();
    }
    float inv = 1.f / red[0];

    const int d = dchunk * 256 + tid;
    const __half* ep = g_enc16 + (size_t)b * (2 * Hh) + d;
    float acc = 0.f;
#pragma unroll 4
    for (int t = 0; t < TIN; t++)
        acc += sAlpha[t] * __half2float(ep[(size_t)t * Bsz * 2 * Hh]);
    __half ctx = __float2half(acc * inv);
    g_x016[b * (2 * Hh + Ee) + d] = ctx;
    g_xl16[b * 3 * Hh + Hh + d] = ctx;
}

// ---------------- wide softmax-V: exp + partial sums (+token/emb on seg 0) ----------------
__global__ __launch_bounds__(256) void smax_exp_kernel(float* __restrict__ outp)
{
    const int b = blockIdx.x, s = blockIdx.y;
    const int tid = threadIdx.x;

    unsigned long long pk = g_maxpack[b];
    float gmax = __uint_as_float((uint32_t)(pk >> 32));

    if (s == 0) {
        int tok = (int)(~(uint32_t)(pk & 0xFFFFFFFFull));
        if (tid == 0) g_tok[b] = tok;
        const __half* er = g_emb16 + (size_t)tok * Ee;
        g_x016[b * (2 * Hh + Ee) + 2 * Hh + tid] = er[tid];
        g_x016[b * (2 * Hh + Ee) + 2 * Hh + tid + 256] = er[tid + 256];
    }

    const float4* lr4 = (const float4*)(g_logits + (size_t)b * Vv + s * SEGV);
    float4* o4 = (float4*)(outp + (size_t)b * Vv + s * SEGV);
    float sum = 0.f;
    for (int i = tid; i < SEGV / 4; i += 256) {
        float4 x = lr4[i];
        float4 e = make_float4(expf(x.x - gmax), expf(x.y - gmax),
                               expf(x.z - gmax), expf(x.w - gmax));
        o4[i] = e;
        sum += e.x + e.y + e.z + e.w;
    }
    __shared__ float rv[256];
    rv[tid] = sum;
    __syncthreads();
    for (int st = 128; st > 0; st >>= 1) {
        if (tid < st) rv[tid] += rv[tid + st];
        __syncthreads();
    }
    if (tid == 0) g_psum[b * NSEG + s] = rv[0];
}

// ---------------- wide softmax-V: rescale (+maxpack reset) ----------------
__global__ __launch_bounds__(256) void smax_scale_kernel(float* __restrict__ outp)
{
    const int b = blockIdx.x, s = blockIdx.y;
    const int tid = threadIdx.x;
    float tot = 0.f;
#pragma unroll
    for (int k = 0; k < NSEG; k++) tot += g_psum[b * NSEG + k];
    const float inv = 1.f / tot;
    if (s == 0 && tid == 0) g_maxpack[b] = 0ull;
    float4* o4 = (float4*)(outp + (size_t)b * Vv + s * SEGV);
    for (int i = tid; i < SEGV / 4; i += 256) {
        float4 e = o4[i];
        o4[i] = make_float4(e.x * inv, e.y * inv, e.z * inv, e.w * inv);
    }
}

// ---------------- host orchestration ----------------
extern "C" void kernel_launch(void* const* d_in, const int* in_sizes, int n_in,
                              void* d_out, int out_size)
{
    const float* enc   = (const float*)d_in[0];
    const float* is_on = (const float*)d_in[1];
    const float* emb   = (const float*)d_in[2];
    const float* A1    = (const float*)d_in[3];
    const float* b1    = (const float*)d_in[4];
    const float* A2    = (const float*)d_in[5];
    const float* b2    = (const float*)d_in[6];
    const float* W_ih0 = (const float*)d_in[7];
    const float* W_ihr = (const float*)d_in[8];
    const float* W_hh  = (const float*)d_in[9];
    const float* b_ih  = (const float*)d_in[10];
    const float* b_hh  = (const float*)d_in[11];
    const float* Wl    = (const float*)d_in[12];
    const float* bl    = (const float*)d_in[13];
    const float* h0    = (const float*)d_in[14];
    const float* c0    = (const float*)d_in[15];
    const float* o0    = (const float*)d_in[16];
    const int*   eos   = (const int*)d_in[17];
    float* out = (float*)d_out;

    uint32_t *pWl, *pWih0, *pWihr, *pWhh, *pA1lo, *pA1hi;
    __half *pEmb16, *pEnc16, *pEncproj16, *pX016, *pXl16, *pHa, *pHb, *pOut16;
    float *pDec, *pC, *pRec, *pLogits;
    unsigned long long* pMaxpack;
    cudaGetSymbolAddress((void**)&pWl, g_Wl16);
    cudaGetSymbolAddress((void**)&pWih0, g_Wih016);
    cudaGetSymbolAddress((void**)&pWihr, g_Wihr16);
    cudaGetSymbolAddress((void**)&pWhh, g_Whh16);
    cudaGetSymbolAddress((void**)&pA1lo, g_A1lo16);
    cudaGetSymbolAddress((void**)&pA1hi, g_A1hi16);
    cudaGetSymbolAddress((void**)&pEmb16, g_emb16);
    cudaGetSymbolAddress((void**)&pEnc16, g_enc16);
    cudaGetSymbolAddress((void**)&pEncproj16, g_encproj16);
    cudaGetSymbolAddress((void**)&pX016, g_x016);
    cudaGetSymbolAddress((void**)&pXl16, g_xl16);
    cudaGetSymbolAddress((void**)&pHa, g_h16a);
    cudaGetSymbolAddress((void**)&pHb, g_h16b);
    cudaGetSymbolAddress((void**)&pOut16, g_out16);
    cudaGetSymbolAddress((void**)&pDec, g_dec);
    cudaGetSymbolAddress((void**)&pC, g_c);
    cudaGetSymbolAddress((void**)&pRec, g_rec);
    cudaGetSymbolAddress((void**)&pLogits, g_logits);
    cudaGetSymbolAddress((void**)&pMaxpack, g_maxpack);

    // smem sizes (all 3-stage)
    const int STG4 = (ASZU + KU * (128 + 8)) * 4;        // 13824 B
    const int STG8 = (ASZU + KU * (256 + 8)) * 4;        // 22016 B
    const int SM4_3 = STG4 * 3;                          // 41472
    const int SM8_3 = STG8 * 3;                          // 66048
    const int SML   = (32 * ASTU + KU * (128 + 8)) * 4 * 3;  // 33792 (MR=32 LSTM)
    cudaFuncSetAttribute(gemmh_kernel<3, 8, 0>, cudaFuncAttributeMaxDynamicSharedMemorySize, SM8_3);
    cudaFuncSetAttribute(gemmh_kernel<1, 4, 0>, cudaFuncAttributeMaxDynamicSharedMemorySize, SM4_3);
    cudaFuncSetAttribute(gemmh_kernel<0, 4, 1>, cudaFuncAttributeMaxDynamicSharedMemorySize, SM4_3);
    cudaFuncSetAttribute(lstm_fused_kernel, cudaFuncAttributeMaxDynamicSharedMemorySize, SML);

    // ---- per-launch weight packing (vectorized) ----
    pack_plain4_kernel<<<dim3(32, 3 * Hh / 2), 256>>>(Wl, pWl, Vv);
    pack_plain4_kernel<<<dim3(1, Hh / 2), 256>>>(A1, pA1lo, Aa);
    pack_plain4_kernel<<<dim3(1, Hh), 256>>>(A1 + (size_t)Hh * Aa, pA1hi, Aa);
    pack_gated2_kernel<<<dim3(8, (2 * Hh + Ee) / 2, 1), 256>>>(W_ih0, pWih0, 0, 0);
    pack_gated2_kernel<<<dim3(8, Hh / 2, 3), 256>>>(W_ihr, pWihr,
        (long)Hh * 4 * Hh, (long)(Hh / 2) * 4 * Hh);
    pack_gated2_kernel<<<dim3(8, Hh / 2, Ll), 256>>>(W_hh, pWhh,
        (long)Hh * 4 * Hh, (long)(Hh / 2) * 4 * Hh);
    cvt_half8_kernel<<<2048, 256>>>(emb, pEmb16, (size_t)Vv * Ee / 8);
    cvt_half8_kernel<<<2048, 256>>>(enc, pEnc16, (size_t)TIN * Bsz * 2 * Hh / 8);

    init_state_kernel<<<(Ll * Bsz * Hh + 255) / 256, 256>>>(h0, c0, o0, eos);

    // enc_proj = enc @ A1[H:]  (8192x512, K=2048) -> fp16
    gemmh_kernel<3, 8, 0><<<dim3(2, 128), 128, SM8_3>>>(
        (const uint32_t*)pEnc16, Hh, 0, pA1hi, 0, Aa,
        nullptr, nullptr, pEncproj16, Aa, 0, 2 * Hh,
        nullptr, nullptr, nullptr, nullptr, nullptr, 0, 0);

    for (int s = 0; s < TOUT; s++) {
        __half* hold = (s & 1) ? pHb : pHa;
        __half* hnew = (s & 1) ? pHa : pHb;

        // merged launch: z<Ll -> rec[l] = h_old[l] @ W_hh[l]; z==Ll -> dec = out_prev @ A1[:H] + b1
        gemmh_kernel<0, 4, 1><<<dim3(32, 1, Ll + 1), 128, SM4_3>>>(
            (const uint32_t*)hold, Hh / 2, (long)Bsz * Hh / 2,
            pWhh, (long)(Hh / 2) * 4 * Hh, 4 * Hh,
            nullptr, pRec, nullptr, 4 * Hh, (long)Bsz * 4 * Hh, Hh,
            nullptr,
            (const uint32_t*)pOut16, pA1lo, pDec, b1, Aa, Aa);

        attn_scores_kernel<<<dim3(TIN, Bsz), 128>>>(is_on, A2, b2);
        attn_context_kernel<<<dim3(Bsz, (2 * Hh) / 256), 256>>>();

        // persistent fused LSTM (all 4 layers, 64 blocks: M split 2 x 32)
        lstm_fused_kernel<<<64, 128, SML>>>(
            (const uint32_t*)pX016, pWih0, pWihr,
            pRec, b_ih, b_hh, pC, hnew);

        // logits = relu([out|context] @ Wl + bl) + fused argmax  (N-split: 250 blocks, NT=4)
        gemmh_kernel<1, 4, 0><<<dim3(Vv / 128, 1), 128, SM4_3>>>(
            (const uint32_t*)pXl16, 3 * Hh / 2, 0, pWl, 0, Vv,
            bl, pLogits, nullptr, Vv, 0, 3 * Hh,
            pMaxpack,
            nullptr, nullptr, nullptr, nullptr, 0, 0);

        // wide softmax: exp (+token/emb) then rescale (+maxpack reset)
        smax_exp_kernel<<<dim3(Bsz, NSEG), 256>>>(out + (size_t)s * Bsz * Vv);
        smax_scale_kernel<<<dim3(Bsz, NSEG), 256>>>(out + (size_t)s * Bsz * Vv);
    }
    (void)in_sizes; (void)n_in; (void)out_size;
}